// round 15
// baseline (speedup 1.0000x reference)
#include <cuda_runtime.h>

#define B_   8
#define S_   32
#define D_   256
#define M_   2048
#define GPB  16      // blocks per batch (slices of M)
#define RPB  128     // rows per slice
#define NT   256     // threads per block
#define PST  272     // floats per partial record
#define NBLK (B_*GPB)
#define NEGINF (__int_as_float(0xff800000))
#define FULLM 0xffffffffu

// ----------------------------- device state -----------------------------
__device__ float g_mem [B_*M_*D_];        // per-batch working rows (filled from regs at t=0)
__device__ float g_qt  [B_*S_*D_];        // (x@Wq+bq)@Wk^T / sqrt(D)
__device__ float g_xg  [B_*S_*D_];        // x@Wg1 + bg
__device__ float g_bgc [D_];              // bv@Wg2
__device__ float g_C   [D_*D_];           // Wv@Wg2
__device__ float g_part[2*B_*GPB*PST];    // partials, double buffered by step parity
__device__ int   g_tidx[2*B_*GPB*8];      // top8 global row ids
__device__ float g_gv  [B_*D_];           // gate vector per batch
__device__ int   g_cnt [2*B_*S_];         // cA[256] then cB[256], zeroed by init

__device__ __forceinline__ int ldacq(const int* p) {
    int v;
    asm volatile("ld.acquire.gpu.global.b32 %0, [%1];" : "=r"(v) : "l"(p) : "memory");
    return v;
}
// release-arrive without the L1D-flushing CCTL.IVALL of __threadfence()
__device__ __forceinline__ void red_release(int* p) {
    asm volatile("red.release.gpu.global.add.s32 [%0], %1;" :: "l"(p), "r"(1) : "memory");
}
__device__ __forceinline__ float dot8(float4 a, float4 b, float4 qa, float4 qb) {
    return a.x*qa.x + a.y*qa.y + a.z*qa.z + a.w*qa.w
         + b.x*qb.x + b.y*qb.y + b.z*qb.z + b.w*qb.w;
}
__device__ __forceinline__ float wredsum(float v) {
    #pragma unroll
    for (int o = 16; o; o >>= 1) v += __shfl_xor_sync(FULLM, v, o);
    return v;
}
__device__ __forceinline__ float wredmax(float v) {
    #pragma unroll
    for (int o = 16; o; o >>= 1) v = fmaxf(v, __shfl_xor_sync(FULLM, v, o));
    return v;
}

// ----------------------------- init kernel (97 blocks) -----------------------------
__global__ void __launch_bounds__(NT)
mal_init(const float* __restrict__ x,  const float* __restrict__ Wq,
         const float* __restrict__ bq, const float* __restrict__ Wk,
         const float* __restrict__ Wv, const float* __restrict__ bv,
         const float* __restrict__ Wg, const float* __restrict__ bg)
{
    __shared__ float s_buf[2048];
    const int bid = blockIdx.x, tid = threadIdx.x;
    const int lane = tid & 31, warp = tid >> 5;

    if (bid == 96) {
        for (int i = tid; i < 2*B_*S_; i += NT) g_cnt[i] = 0;
        float acc = 0.f;
        #pragma unroll 16
        for (int j = 0; j < D_; ++j) acc += bv[j] * Wg[(D_ + j)*D_ + tid];
        g_bgc[tid] = acc;
        return;
    }
    const int which = bid >> 5;               // 0: qt-chain, 1: xg, 2: C
    const int sub   = bid & 31;
    const int r0    = sub * 8;
    const float* srcA = (which == 2) ? (Wv + r0*D_) : (x + r0*D_);
    for (int i = tid; i < 2048; i += NT) s_buf[i] = srcA[i];
    __syncthreads();
    const float* Wcol = (which == 0) ? Wq : (which == 1 ? Wg : (Wg + D_*D_));
    float acc[8];
    #pragma unroll
    for (int r = 0; r < 8; ++r) acc[r] = 0.f;
    #pragma unroll 16
    for (int j = 0; j < D_; ++j) {
        float w = Wcol[j*D_ + tid];
        #pragma unroll
        for (int r = 0; r < 8; ++r) acc[r] += s_buf[r*D_ + j] * w;
    }
    if (which == 1) {
        float bb = bg[tid];
        #pragma unroll
        for (int r = 0; r < 8; ++r) g_xg[(r0+r)*D_ + tid] = acc[r] + bb;
    } else if (which == 2) {
        #pragma unroll
        for (int r = 0; r < 8; ++r) g_C[(r0+r)*D_ + tid] = acc[r];
    } else {
        float bb = bq[tid];
        __syncthreads();
        #pragma unroll
        for (int r = 0; r < 8; ++r) s_buf[r*D_ + tid] = acc[r] + bb;
        __syncthreads();
        float4 t0[8], t1[8];
        #pragma unroll
        for (int r = 0; r < 8; ++r) {
            t0[r] = *(const float4*)(s_buf + r*D_ + lane*4);
            t1[r] = *(const float4*)(s_buf + r*D_ + 128 + lane*4);
        }
        int d = warp * 32;
        float4 w0 = *(const float4*)(Wk + d*D_ + lane*4);
        float4 w1 = *(const float4*)(Wk + d*D_ + 128 + lane*4);
        for (int dd = 0; dd < 32; ++dd) {
            float4 c0 = w0, c1 = w1;
            if (dd < 31) {
                w0 = *(const float4*)(Wk + (d+1)*D_ + lane*4);
                w1 = *(const float4*)(Wk + (d+1)*D_ + 128 + lane*4);
            }
            float dt[8];
            #pragma unroll
            for (int r = 0; r < 8; ++r) {
                dt[r] = t0[r].x*c0.x + t0[r].y*c0.y + t0[r].z*c0.z + t0[r].w*c0.w
                      + t1[r].x*c1.x + t1[r].y*c1.y + t1[r].z*c1.z + t1[r].w*c1.w;
                dt[r] = wredsum(dt[r]);
            }
            if (lane == 0) {
                #pragma unroll
                for (int r = 0; r < 8; ++r) g_qt[(r0+r)*D_ + d] = dt[r] * 0.0625f;
            }
            ++d;
        }
    }
}

// ----------------------------- main persistent kernel -----------------------------
__global__ void __launch_bounds__(NT, 1)
mal_main(const float* __restrict__ x, const float* __restrict__ memory,
         const float* __restrict__ Wv, const float* __restrict__ bv,
         float* __restrict__ out)
{
    __shared__ float s_wacc[8][D_];
    __shared__ float s_wm[8], s_ws[8];
    __shared__ float s_lg[2][128];                 // logits, double buffered by step
    __shared__ unsigned long long s_cand[32];      // top-8-per-warp survivors
    __shared__ int   s_sel[8];
    __shared__ float s_p[D_];
    __shared__ float s_red[NT];

    const int tid  = threadIdx.x, lane = tid & 31, warp = tid >> 5;
    const int bid  = blockIdx.x;
    const int b    = bid >> 4;
    const int blk  = bid & 15;
    int* cA        = g_cnt + b * S_;
    int* cB        = g_cnt + B_*S_ + b * S_;
    const int d0   = lane * 4;
    const int d1   = 128 + lane * 4;
    float* rowp    = g_mem + ((size_t)b*M_ + blk*RPB + warp*16) * D_;

    // ---- prologue: rows copied memory -> g_mem, logits for t=0 ----
    {
        const float4 qa = *(const float4*)(g_qt + (b*S_)*D_ + d0);
        const float4 qb = *(const float4*)(g_qt + (b*S_)*D_ + d1);
        const float* src = memory + (blk*RPB + warp*16) * D_;
        #pragma unroll
        for (int r = 0; r < 16; ++r) {
            float4 fa = *(const float4*)(src + r*D_ + d0);
            float4 fb = *(const float4*)(src + r*D_ + d1);
            *(float4*)(rowp + r*D_ + d0) = fa;
            *(float4*)(rowp + r*D_ + d1) = fb;
            float dt = wredsum(dot8(fa, fb, qa, qb));
            if (lane == 0) s_lg[0][warp*16 + r] = dt;
        }
        __syncwarp();
    }

    for (int t = 0; t < S_; ++t) {
        const int cur = t & 1, nxt = cur ^ 1;
        float* partbase = g_part + cur*(B_*GPB*PST);
        float* part     = partbase + bid * PST;
        int*   tidx     = g_tidx + cur*(B_*GPB*8);

        // ---- 1. owners apply step t-1's gated updates, correct dirty logits ----
        if (t > 0) {
            bool own = false;
            #pragma unroll
            for (int k = 0; k < 8; ++k) own |= ((s_sel[k] >> 7) == blk);
            if (own) {                                   // block-uniform branch
                if (tid == 0) { while (ldacq(&cB[t-1]) < GPB) { } }
                __syncthreads();
                float4 g0 = __ldcg((const float4*)(g_gv + b*D_ + d0));
                float4 g1 = __ldcg((const float4*)(g_gv + b*D_ + d1));
                float4 x0 = __ldg ((const float4*)(x + (size_t)(b*S_ + t-1)*D_ + d0));
                float4 x1 = __ldg ((const float4*)(x + (size_t)(b*S_ + t-1)*D_ + d1));
                const float4 qa = *(const float4*)(g_qt + (b*S_ + t)*D_ + d0);
                const float4 qb = *(const float4*)(g_qt + (b*S_ + t)*D_ + d1);
                #pragma unroll
                for (int k = 0; k < 8; ++k) {
                    int gi = s_sel[k];
                    if ((gi >> 7) == blk && ((gi >> 4) & 7) == warp) {
                        int r = gi & 15;
                        float4 fa = *(float4*)(rowp + r*D_ + d0);
                        float4 fb = *(float4*)(rowp + r*D_ + d1);
                        fa.x += g0.x*(x0.x - fa.x); fa.y += g0.y*(x0.y - fa.y);
                        fa.z += g0.z*(x0.z - fa.z); fa.w += g0.w*(x0.w - fa.w);
                        fb.x += g1.x*(x1.x - fb.x); fb.y += g1.y*(x1.y - fb.y);
                        fb.z += g1.z*(x1.z - fb.z); fb.w += g1.w*(x1.w - fb.w);
                        *(float4*)(rowp + r*D_ + d0) = fa;
                        *(float4*)(rowp + r*D_ + d1) = fb;
                        float dt = wredsum(dot8(fa, fb, qa, qb));
                        if (lane == 0) s_lg[cur][warp*16 + r] = dt;
                    }
                }
                __syncwarp();
            }
        }

        // ---- 2. lane-parallel softmax pieces from smem logits ----
        float lv = (lane < 16) ? s_lg[cur][warp*16 + lane] : NEGINF;
        float mw = wredmax(lv);
        float ev = (lane < 16) ? __expf(lv - mw) : 0.f;
        float sw = wredsum(ev);

        // ---- 3. weighted-sum sweep (FMA only, no reductions) ----
        {
            float4 A = {0,0,0,0}, Bb = {0,0,0,0};
            #pragma unroll
            for (int r = 0; r < 16; ++r) {
                float er = __shfl_sync(FULLM, ev, r);
                float4 fa = *(const float4*)(rowp + r*D_ + d0);
                float4 fb = *(const float4*)(rowp + r*D_ + d1);
                A.x += er*fa.x; A.y += er*fa.y; A.z += er*fa.z; A.w += er*fa.w;
                Bb.x += er*fb.x; Bb.y += er*fb.y; Bb.z += er*fb.z; Bb.w += er*fb.w;
            }
            *(float4*)&s_wacc[warp][d0] = A;
            *(float4*)&s_wacc[warp][d1] = Bb;
            if (lane == 0) { s_wm[warp] = mw; s_ws[warp] = sw; }
        }
        __syncthreads();                                            // S1

        // ---- 4. stage 2: rescaled partial + local top-8 ----
        unsigned long long key1 = 0;
        {
            float m0 = fmaxf(fmaxf(s_wm[0], s_wm[1]), fmaxf(s_wm[2], s_wm[3]));
            float m1 = fmaxf(fmaxf(s_wm[4], s_wm[5]), fmaxf(s_wm[6], s_wm[7]));
            float bm = fmaxf(m0, m1);
            float scv = (lane < 8) ? __expf(s_wm[lane] - bm) : 0.f;
            float pv = 0.f;
            #pragma unroll
            for (int w = 0; w < 8; ++w)
                pv += s_wacc[w][tid] * __shfl_sync(FULLM, scv, w);
            part[2 + tid] = pv;
            if (warp == 0) {
                float t8 = (lane < 8) ? scv * s_ws[lane] : 0.f;
                t8 = wredsum(t8);
                if (lane == 0) { part[0] = bm; part[1] = t8; }
            }
            if (tid < 128) {
                unsigned fb = __float_as_uint(s_lg[cur][tid]);
                fb ^= (fb & 0x80000000u) ? 0xFFFFFFFFu : 0x80000000u;
                key1 = ((unsigned long long)fb << 32) | (unsigned)(~tid);
            }
        }
        if (tid < 128) {
            int rk = 0;
            #pragma unroll
            for (int i = 1; i < 32; ++i) {
                unsigned long long o = __shfl_sync(FULLM, key1, (lane + i) & 31);
                rk += (o > key1);
            }
            if (rk < 8) s_cand[warp*8 + rk] = key1;
        }
        __syncthreads();                                            // S2
        if (warp == 0) {
            unsigned long long k2 = s_cand[lane];
            int rk = 0;
            #pragma unroll
            for (int i = 1; i < 32; ++i) {
                unsigned long long o = __shfl_sync(FULLM, k2, (lane + i) & 31);
                rk += (o > k2);
            }
            if (rk < 8) {
                unsigned fb = (unsigned)(k2 >> 32);
                fb ^= (fb & 0x80000000u) ? 0x80000000u : 0xFFFFFFFFu;
                int c = (int)(~((unsigned)k2)) & 127;
                part[258 + rk] = __uint_as_float(fb);
                tidx[bid*8 + rk] = blk*RPB + c;
            }
        }
        __syncthreads();                                            // S3

        // ---- 5. release barrier A EARLY ----
        if (tid == 0) red_release(&cA[t]);

        // ---- 6a. next-step logits rows 0-7 (hidden behind barrier propagation) ----
        const float4 qna = (t + 1 < S_) ? *(const float4*)(g_qt + (b*S_ + t+1)*D_ + d0)
                                        : make_float4(0,0,0,0);
        const float4 qnb = (t + 1 < S_) ? *(const float4*)(g_qt + (b*S_ + t+1)*D_ + d1)
                                        : make_float4(0,0,0,0);
        if (t + 1 < S_) {
            #pragma unroll
            for (int r = 0; r < 8; ++r) {
                float4 fa = *(const float4*)(rowp + r*D_ + d0);
                float4 fb = *(const float4*)(rowp + r*D_ + d1);
                float dt = wredsum(dot8(fa, fb, qna, qnb));
                if (lane == 0) s_lg[nxt][warp*16 + r] = dt;
            }
        }

        // ---- 7. wait barrier A ----
        if (tid == 0) { while (ldacq(&cA[t]) < GPB) { } }
        __syncthreads();                                            // S4

        // ---- 8. merge: issue bm/sw loads, hide latency with logits rows 8-15 ----
        {
            float lv2 = (lane < 16) ? __ldcg(&partbase[(b*GPB + lane)*PST])     : NEGINF;
            float sv2 = (lane < 16) ? __ldcg(&partbase[(b*GPB + lane)*PST + 1]) : 0.f;

            // 6b. next-step logits rows 8-15 (hide merge-read latency)
            if (t + 1 < S_) {
                #pragma unroll
                for (int r = 8; r < 16; ++r) {
                    float4 fa = *(const float4*)(rowp + r*D_ + d0);
                    float4 fb = *(const float4*)(rowp + r*D_ + d1);
                    float dt = wredsum(dot8(fa, fb, qna, qnb));
                    if (lane == 0) s_lg[nxt][warp*16 + r] = dt;
                }
            }

            float Mx = wredmax(lv2);
            float scv2 = (lane < 16) ? __expf(lv2 - Mx) : 0.f;
            float Ssum = wredsum(scv2 * sv2);
            float invS = 1.0f / Ssum;
            float pv = 0.f;
            #pragma unroll
            for (int i = 0; i < 16; ++i)
                pv += __ldcg(&partbase[(b*GPB + i)*PST + 2 + tid]) * __shfl_sync(FULLM, scv2, i);
            s_p[tid] = pv * invS;
        }
        // global top-8, stage A (candidates from all 16 blocks)
        if (tid < 128) {
            int i = tid >> 3, j = tid & 7;
            float cv = __ldcg(&partbase[(b*GPB + i)*PST + 258 + j]);
            int   ci = __ldcg(&tidx[(b*GPB + i)*8 + j]);
            unsigned fb = __float_as_uint(cv);
            fb ^= (fb & 0x80000000u) ? 0xFFFFFFFFu : 0x80000000u;
            unsigned long long key2 = ((unsigned long long)fb << 32) | (unsigned)(~ci);
            int rk = 0;
            #pragma unroll
            for (int i2 = 1; i2 < 32; ++i2) {
                unsigned long long o = __shfl_sync(FULLM, key2, (lane + i2) & 31);
                rk += (o > key2);
            }
            if (rk < 8) s_cand[warp*8 + rk] = key2;
        }
        __syncthreads();                                            // S5
        // global top-8, stage B (warp 0) + out/gate slice GEMV (all warps)
        if (warp == 0) {
            unsigned long long k2 = s_cand[lane];
            int rk = 0;
            #pragma unroll
            for (int i = 1; i < 32; ++i) {
                unsigned long long o = __shfl_sync(FULLM, k2, (lane + i) & 31);
                rk += (o > k2);
            }
            if (rk < 8) s_sel[rk] = (int)(~((unsigned)k2));
        }
        {
            const int dbase = blk * 16;
            const float* Mp = (lane < 16) ? (Wv + dbase + lane)
                                          : (g_C + dbase + (lane - 16));
            float acc = 0.f;
            const int k0 = warp * 32;
            #pragma unroll
            for (int kk = 0; kk < 32; ++kk)
                acc += s_p[k0 + kk] * Mp[(k0 + kk)*D_];
            s_red[tid] = acc;
        }
        __syncthreads();                                            // S6

        // ---- 9. warp 0: gate slice + EARLY cB release; warp 1: out store ----
        if (warp == 0) {
            if (lane >= 16) {
                float tot = 0.f;
                #pragma unroll
                for (int w = 0; w < 8; ++w) tot += s_red[w*32 + lane];
                int d = blk * 16 + lane - 16;
                float z = g_xg[(b*S_ + t)*D_ + d] + g_bgc[d] + tot;
                g_gv[b*D_ + d] = 1.0f / (1.0f + __expf(-z));
            }
            __syncwarp();
            if (lane == 0) red_release(&cB[t]);       // owners wait at t+1
        } else if (warp == 1 && lane < 16) {
            float tot = 0.f;
            #pragma unroll
            for (int w = 0; w < 8; ++w) tot += s_red[w*32 + lane];
            const int dbase = blk * 16;
            out[(b*S_ + t)*D_ + dbase + lane] = tot + __ldg(&bv[dbase + lane]);
        }
        // no trailing sync: warps 2-7 proceed; all shared-buffer reuse in the
        // next iteration is separated from this step's readers by S1..S6.
    }
}

// ----------------------------- launch -----------------------------
extern "C" void kernel_launch(void* const* d_in, const int* in_sizes, int n_in,
                              void* d_out, int out_size)
{
    const float* x      = (const float*)d_in[0];
    const float* memory = (const float*)d_in[1];
    const float* Wq     = (const float*)d_in[2];
    const float* bq     = (const float*)d_in[3];
    const float* Wk     = (const float*)d_in[4];
    // d_in[5] = bk : constant logit shift; softmax/top-k invariant -> unused
    const float* Wv     = (const float*)d_in[6];
    const float* bv     = (const float*)d_in[7];
    const float* Wg     = (const float*)d_in[8];
    const float* bg     = (const float*)d_in[9];
    float* out = (float*)d_out;

    mal_init<<<97, NT>>>(x, Wq, bq, Wk, Wv, bv, Wg, bg);
    mal_main<<<NBLK, NT>>>(x, memory, Wv, bv, out);
}

// round 16
// speedup vs baseline: 1.4671x; 1.4671x over previous
#include <cuda_runtime.h>

#define B_   8
#define S_   32
#define D_   256
#define M_   2048
#define GPB  16      // blocks per batch (slices of M)
#define RPB  128     // rows per slice
#define NT   256     // threads per block
#define PST  272     // floats per partial record
#define NBLK (B_*GPB)
#define NEGINF (__int_as_float(0xff800000))
#define FULLM 0xffffffffu

// ----------------------------- device state -----------------------------
__device__ float g_mem [B_*M_*D_];        // per-batch working rows (filled from regs at t=0)
__device__ float g_qt  [B_*S_*D_];        // (x@Wq+bq)@Wk^T / sqrt(D)
__device__ float g_xg  [B_*S_*D_];        // x@Wg1 + bg
__device__ float g_bgc [D_];              // bv@Wg2
__device__ float g_C   [D_*D_];           // Wv@Wg2
__device__ float g_part[2*B_*GPB*PST];    // partials, double buffered by step parity
__device__ int   g_tidx[2*B_*GPB*8];      // top8 global row ids
__device__ float g_gv  [B_*D_];           // gate vector per batch
__device__ int   g_cnt [2*B_*S_];         // cA[256] then cB[256], zeroed by init

__device__ __forceinline__ int ldacq(const int* p) {
    int v;
    asm volatile("ld.acquire.gpu.global.b32 %0, [%1];" : "=r"(v) : "l"(p) : "memory");
    return v;
}
// release-arrive without the L1D-flushing CCTL.IVALL of __threadfence()
__device__ __forceinline__ void red_release(int* p) {
    asm volatile("red.release.gpu.global.add.s32 [%0], %1;" :: "l"(p), "r"(1) : "memory");
}
__device__ __forceinline__ float dot8(float4 a, float4 b, float4 qa, float4 qb) {
    return a.x*qa.x + a.y*qa.y + a.z*qa.z + a.w*qa.w
         + b.x*qb.x + b.y*qb.y + b.z*qb.z + b.w*qb.w;
}
__device__ __forceinline__ float wredsum(float v) {
    #pragma unroll
    for (int o = 16; o; o >>= 1) v += __shfl_xor_sync(FULLM, v, o);
    return v;
}
__device__ __forceinline__ float wredmax(float v) {
    #pragma unroll
    for (int o = 16; o; o >>= 1) v = fmaxf(v, __shfl_xor_sync(FULLM, v, o));
    return v;
}

// ----------------------------- init kernel (97 blocks) -----------------------------
__global__ void __launch_bounds__(NT)
mal_init(const float* __restrict__ x,  const float* __restrict__ Wq,
         const float* __restrict__ bq, const float* __restrict__ Wk,
         const float* __restrict__ Wv, const float* __restrict__ bv,
         const float* __restrict__ Wg, const float* __restrict__ bg)
{
    __shared__ float s_buf[2048];
    const int bid = blockIdx.x, tid = threadIdx.x;
    const int lane = tid & 31, warp = tid >> 5;

    if (bid == 96) {
        for (int i = tid; i < 2*B_*S_; i += NT) g_cnt[i] = 0;
        float acc = 0.f;
        #pragma unroll 16
        for (int j = 0; j < D_; ++j) acc += bv[j] * Wg[(D_ + j)*D_ + tid];
        g_bgc[tid] = acc;
        return;
    }
    const int which = bid >> 5;               // 0: qt-chain, 1: xg, 2: C
    const int sub   = bid & 31;
    const int r0    = sub * 8;
    const float* srcA = (which == 2) ? (Wv + r0*D_) : (x + r0*D_);
    for (int i = tid; i < 2048; i += NT) s_buf[i] = srcA[i];
    __syncthreads();
    const float* Wcol = (which == 0) ? Wq : (which == 1 ? Wg : (Wg + D_*D_));
    float acc[8];
    #pragma unroll
    for (int r = 0; r < 8; ++r) acc[r] = 0.f;
    #pragma unroll 16
    for (int j = 0; j < D_; ++j) {
        float w = Wcol[j*D_ + tid];
        #pragma unroll
        for (int r = 0; r < 8; ++r) acc[r] += s_buf[r*D_ + j] * w;
    }
    if (which == 1) {
        float bb = bg[tid];
        #pragma unroll
        for (int r = 0; r < 8; ++r) g_xg[(r0+r)*D_ + tid] = acc[r] + bb;
    } else if (which == 2) {
        #pragma unroll
        for (int r = 0; r < 8; ++r) g_C[(r0+r)*D_ + tid] = acc[r];
    } else {
        float bb = bq[tid];
        __syncthreads();
        #pragma unroll
        for (int r = 0; r < 8; ++r) s_buf[r*D_ + tid] = acc[r] + bb;
        __syncthreads();
        float4 t0[8], t1[8];
        #pragma unroll
        for (int r = 0; r < 8; ++r) {
            t0[r] = *(const float4*)(s_buf + r*D_ + lane*4);
            t1[r] = *(const float4*)(s_buf + r*D_ + 128 + lane*4);
        }
        int d = warp * 32;
        float4 w0 = *(const float4*)(Wk + d*D_ + lane*4);
        float4 w1 = *(const float4*)(Wk + d*D_ + 128 + lane*4);
        for (int dd = 0; dd < 32; ++dd) {
            float4 c0 = w0, c1 = w1;
            if (dd < 31) {
                w0 = *(const float4*)(Wk + (d+1)*D_ + lane*4);
                w1 = *(const float4*)(Wk + (d+1)*D_ + 128 + lane*4);
            }
            float dt[8];
            #pragma unroll
            for (int r = 0; r < 8; ++r) {
                dt[r] = t0[r].x*c0.x + t0[r].y*c0.y + t0[r].z*c0.z + t0[r].w*c0.w
                      + t1[r].x*c1.x + t1[r].y*c1.y + t1[r].z*c1.z + t1[r].w*c1.w;
                dt[r] = wredsum(dt[r]);
            }
            if (lane == 0) {
                #pragma unroll
                for (int r = 0; r < 8; ++r) g_qt[(r0+r)*D_ + d] = dt[r] * 0.0625f;
            }
            ++d;
        }
    }
}

// ----------------------------- main persistent kernel -----------------------------
__global__ void __launch_bounds__(NT, 1)
mal_main(const float* __restrict__ x, const float* __restrict__ memory,
         const float* __restrict__ Wv, const float* __restrict__ bv,
         float* __restrict__ out)
{
    __shared__ float s_wacc[8][D_];
    __shared__ float s_wm[8], s_ws[8];
    __shared__ float s_lg[2][128];                 // logits, double buffered by step
    __shared__ unsigned long long s_cand[32];      // top-8-per-warp survivors
    __shared__ int   s_sel[8];
    __shared__ float s_p[D_];
    __shared__ float s_red[NT];

    const int tid  = threadIdx.x, lane = tid & 31, warp = tid >> 5;
    const int bid  = blockIdx.x;
    const int b    = bid >> 4;
    const int blk  = bid & 15;
    int* cA        = g_cnt + b * S_;
    int* cB        = g_cnt + B_*S_ + b * S_;
    const int d0   = lane * 4;
    const int d1   = 128 + lane * 4;
    float* rowp    = g_mem + ((size_t)b*M_ + blk*RPB + warp*16) * D_;

    // ---- prologue: rows copied memory -> g_mem, logits for t=0 ----
    {
        const float4 qa = *(const float4*)(g_qt + (b*S_)*D_ + d0);
        const float4 qb = *(const float4*)(g_qt + (b*S_)*D_ + d1);
        const float* src = memory + (blk*RPB + warp*16) * D_;
        #pragma unroll
        for (int r = 0; r < 16; ++r) {
            float4 fa = *(const float4*)(src + r*D_ + d0);
            float4 fb = *(const float4*)(src + r*D_ + d1);
            *(float4*)(rowp + r*D_ + d0) = fa;
            *(float4*)(rowp + r*D_ + d1) = fb;
            float dt = wredsum(dot8(fa, fb, qa, qb));
            if (lane == 0) s_lg[0][warp*16 + r] = dt;
        }
        __syncwarp();
    }

    for (int t = 0; t < S_; ++t) {
        const int cur = t & 1, nxt = cur ^ 1;
        float* partbase = g_part + cur*(B_*GPB*PST);
        float* part     = partbase + bid * PST;
        int*   tidx     = g_tidx + cur*(B_*GPB*8);

        // ---- 1. owners apply step t-1's gated updates, correct dirty logits ----
        if (t > 0) {
            bool own = false;
            #pragma unroll
            for (int k = 0; k < 8; ++k) own |= ((s_sel[k] >> 7) == blk);
            if (own) {                                   // block-uniform branch
                // hoist loads that do NOT depend on gv above the wait
                float4 x0 = __ldg ((const float4*)(x + (size_t)(b*S_ + t-1)*D_ + d0));
                float4 x1 = __ldg ((const float4*)(x + (size_t)(b*S_ + t-1)*D_ + d1));
                const float4 qa = *(const float4*)(g_qt + (b*S_ + t)*D_ + d0);
                const float4 qb = *(const float4*)(g_qt + (b*S_ + t)*D_ + d1);
                if (tid == 0) { while (ldacq(&cB[t-1]) < GPB) { } }
                __syncthreads();
                float4 g0 = __ldcg((const float4*)(g_gv + b*D_ + d0));
                float4 g1 = __ldcg((const float4*)(g_gv + b*D_ + d1));
                #pragma unroll
                for (int k = 0; k < 8; ++k) {
                    int gi = s_sel[k];
                    if ((gi >> 7) == blk && ((gi >> 4) & 7) == warp) {
                        int r = gi & 15;
                        float4 fa = *(float4*)(rowp + r*D_ + d0);
                        float4 fb = *(float4*)(rowp + r*D_ + d1);
                        fa.x += g0.x*(x0.x - fa.x); fa.y += g0.y*(x0.y - fa.y);
                        fa.z += g0.z*(x0.z - fa.z); fa.w += g0.w*(x0.w - fa.w);
                        fb.x += g1.x*(x1.x - fb.x); fb.y += g1.y*(x1.y - fb.y);
                        fb.z += g1.z*(x1.z - fb.z); fb.w += g1.w*(x1.w - fb.w);
                        *(float4*)(rowp + r*D_ + d0) = fa;
                        *(float4*)(rowp + r*D_ + d1) = fb;
                        float dt = wredsum(dot8(fa, fb, qa, qb));
                        if (lane == 0) s_lg[cur][warp*16 + r] = dt;
                    }
                }
                __syncwarp();
            }
        }

        // ---- 2. lane-parallel softmax pieces from smem logits ----
        float lv = (lane < 16) ? s_lg[cur][warp*16 + lane] : NEGINF;
        float mw = wredmax(lv);
        float ev = (lane < 16) ? __expf(lv - mw) : 0.f;
        float sw = wredsum(ev);

        // ---- 3. weighted-sum sweep (FMA only, no reductions) ----
        {
            float4 A = {0,0,0,0}, Bb = {0,0,0,0};
            #pragma unroll
            for (int r = 0; r < 16; ++r) {
                float er = __shfl_sync(FULLM, ev, r);
                float4 fa = *(const float4*)(rowp + r*D_ + d0);
                float4 fb = *(const float4*)(rowp + r*D_ + d1);
                A.x += er*fa.x; A.y += er*fa.y; A.z += er*fa.z; A.w += er*fa.w;
                Bb.x += er*fb.x; Bb.y += er*fb.y; Bb.z += er*fb.z; Bb.w += er*fb.w;
            }
            *(float4*)&s_wacc[warp][d0] = A;
            *(float4*)&s_wacc[warp][d1] = Bb;
            if (lane == 0) { s_wm[warp] = mw; s_ws[warp] = sw; }
        }
        __syncthreads();                                            // S1

        // ---- 4. stage 2: rescaled partial + local top-8 ----
        unsigned long long key1 = 0;
        {
            float m0 = fmaxf(fmaxf(s_wm[0], s_wm[1]), fmaxf(s_wm[2], s_wm[3]));
            float m1 = fmaxf(fmaxf(s_wm[4], s_wm[5]), fmaxf(s_wm[6], s_wm[7]));
            float bm = fmaxf(m0, m1);
            float scv = (lane < 8) ? __expf(s_wm[lane] - bm) : 0.f;
            float pv = 0.f;
            #pragma unroll
            for (int w = 0; w < 8; ++w)
                pv += s_wacc[w][tid] * __shfl_sync(FULLM, scv, w);
            part[2 + tid] = pv;
            if (warp == 0) {
                float t8 = (lane < 8) ? scv * s_ws[lane] : 0.f;
                t8 = wredsum(t8);
                if (lane == 0) { part[0] = bm; part[1] = t8; }
            }
            if (tid < 128) {
                unsigned fb = __float_as_uint(s_lg[cur][tid]);
                fb ^= (fb & 0x80000000u) ? 0xFFFFFFFFu : 0x80000000u;
                key1 = ((unsigned long long)fb << 32) | (unsigned)(~tid);
            }
        }
        if (tid < 128) {
            int rk = 0;
            #pragma unroll
            for (int i = 1; i < 32; ++i) {
                unsigned long long o = __shfl_sync(FULLM, key1, (lane + i) & 31);
                rk += (o > key1);
            }
            if (rk < 8) s_cand[warp*8 + rk] = key1;
        }
        __syncthreads();                                            // S2
        if (warp == 0) {
            unsigned long long k2 = s_cand[lane];
            int rk = 0;
            #pragma unroll
            for (int i = 1; i < 32; ++i) {
                unsigned long long o = __shfl_sync(FULLM, k2, (lane + i) & 31);
                rk += (o > k2);
            }
            if (rk < 8) {
                unsigned fb = (unsigned)(k2 >> 32);
                fb ^= (fb & 0x80000000u) ? 0x80000000u : 0xFFFFFFFFu;
                int c = (int)(~((unsigned)k2)) & 127;
                part[258 + rk] = __uint_as_float(fb);
                tidx[bid*8 + rk] = blk*RPB + c;
            }
        }
        __syncthreads();                                            // S3

        // ---- 5. release barrier A EARLY ----
        if (tid == 0) red_release(&cA[t]);

        // ---- 6. next-step logits (hidden behind barrier propagation) ----
        if (t + 1 < S_) {
            const float4 qa = *(const float4*)(g_qt + (b*S_ + t+1)*D_ + d0);
            const float4 qb = *(const float4*)(g_qt + (b*S_ + t+1)*D_ + d1);
            #pragma unroll
            for (int r = 0; r < 16; ++r) {
                float4 fa = *(const float4*)(rowp + r*D_ + d0);
                float4 fb = *(const float4*)(rowp + r*D_ + d1);
                float dt = wredsum(dot8(fa, fb, qa, qb));
                if (lane == 0) s_lg[nxt][warp*16 + r] = dt;
            }
        }

        // ---- 7. wait barrier A ----
        if (tid == 0) { while (ldacq(&cA[t]) < GPB) { } }
        __syncthreads();                                            // S4

        // ---- 8. merge: issue ALL merge loads up front (bm/sw + candidates) ----
        float cv; int ci;
        {
            float lv2 = (lane < 16) ? __ldcg(&partbase[(b*GPB + lane)*PST])     : NEGINF;
            float sv2 = (lane < 16) ? __ldcg(&partbase[(b*GPB + lane)*PST + 1]) : 0.f;
            if (tid < 128) {                       // candidate loads overlap bm/sw
                int i = tid >> 3, j = tid & 7;
                cv = __ldcg(&partbase[(b*GPB + i)*PST + 258 + j]);
                ci = __ldcg(&tidx[(b*GPB + i)*8 + j]);
            }
            float Mx = wredmax(lv2);
            float scv2 = (lane < 16) ? __expf(lv2 - Mx) : 0.f;
            float Ssum = wredsum(scv2 * sv2);
            float invS = 1.0f / Ssum;
            float pv = 0.f;
            #pragma unroll
            for (int i = 0; i < 16; ++i)
                pv += __ldcg(&partbase[(b*GPB + i)*PST + 2 + tid]) * __shfl_sync(FULLM, scv2, i);
            s_p[tid] = pv * invS;
        }
        // global top-8, stage A (candidates preloaded)
        if (tid < 128) {
            unsigned fb = __float_as_uint(cv);
            fb ^= (fb & 0x80000000u) ? 0xFFFFFFFFu : 0x80000000u;
            unsigned long long key2 = ((unsigned long long)fb << 32) | (unsigned)(~ci);
            int rk = 0;
            #pragma unroll
            for (int i2 = 1; i2 < 32; ++i2) {
                unsigned long long o = __shfl_sync(FULLM, key2, (lane + i2) & 31);
                rk += (o > key2);
            }
            if (rk < 8) s_cand[warp*8 + rk] = key2;
        }
        __syncthreads();                                            // S5
        // global top-8, stage B (warp 0) + out/gate slice GEMV (all warps)
        if (warp == 0) {
            unsigned long long k2 = s_cand[lane];
            int rk = 0;
            #pragma unroll
            for (int i = 1; i < 32; ++i) {
                unsigned long long o = __shfl_sync(FULLM, k2, (lane + i) & 31);
                rk += (o > k2);
            }
            if (rk < 8) s_sel[rk] = (int)(~((unsigned)k2));
        }
        {
            const int dbase = blk * 16;
            const float* Mp = (lane < 16) ? (Wv + dbase + lane)
                                          : (g_C + dbase + (lane - 16));
            float acc = 0.f;
            const int k0 = warp * 32;
            #pragma unroll
            for (int kk = 0; kk < 32; ++kk)
                acc += s_p[k0 + kk] * Mp[(k0 + kk)*D_];
            s_red[tid] = acc;
        }
        __syncthreads();                                            // S6

        // ---- 9. warp 0: gate slice + EARLY cB release; warp 1: out store ----
        if (warp == 0) {
            if (lane >= 16) {
                float tot = 0.f;
                #pragma unroll
                for (int w = 0; w < 8; ++w) tot += s_red[w*32 + lane];
                int d = blk * 16 + lane - 16;
                float z = g_xg[(b*S_ + t)*D_ + d] + g_bgc[d] + tot;
                g_gv[b*D_ + d] = 1.0f / (1.0f + __expf(-z));
            }
            __syncwarp();
            if (lane == 0) red_release(&cB[t]);       // owners wait at t+1
        } else if (warp == 1 && lane < 16) {
            float tot = 0.f;
            #pragma unroll
            for (int w = 0; w < 8; ++w) tot += s_red[w*32 + lane];
            const int dbase = blk * 16;
            out[(b*S_ + t)*D_ + dbase + lane] = tot + __ldg(&bv[dbase + lane]);
        }
        __syncthreads();                                            // S7 (kept: R14 showed
                                                                    // removal regresses)
    }
}

// ----------------------------- launch -----------------------------
extern "C" void kernel_launch(void* const* d_in, const int* in_sizes, int n_in,
                              void* d_out, int out_size)
{
    const float* x      = (const float*)d_in[0];
    const float* memory = (const float*)d_in[1];
    const float* Wq     = (const float*)d_in[2];
    const float* bq     = (const float*)d_in[3];
    const float* Wk     = (const float*)d_in[4];
    // d_in[5] = bk : constant logit shift; softmax/top-k invariant -> unused
    const float* Wv     = (const float*)d_in[6];
    const float* bv     = (const float*)d_in[7];
    const float* Wg     = (const float*)d_in[8];
    const float* bg     = (const float*)d_in[9];
    float* out = (float*)d_out;

    mal_init<<<97, NT>>>(x, Wq, bq, Wk, Wv, bv, Wg, bg);
    mal_main<<<NBLK, NT>>>(x, memory, Wv, bv, out);
}